// round 5
// baseline (speedup 1.0000x reference)
#include <cuda_runtime.h>
#include <cuda_fp16.h>
#include <math.h>

#define T_STEPS 1024
#define NMC     32768
#define NCTA    148
#define NPAIRS  7              // warp pairs per CTA
#define TPB     (NPAIRS * 64)  // 448
#define NPATH_W 32             // paths per warp (pair covers same 32 paths)

// ---- scratch (__device__ globals) -------------------------------------------
// layer-1 per-step consts, 0.5-scaled, packed per (net,t,kt,tg):
//   uint2{ half2 pair(kt*8+tg), half2 pair(kt*8+tg+4) }
__device__ uint2   g_c1p[2 * T_STEPS * 16];
__device__ __half2 g_w05h[2 * 32];           // 0.5 * W1[z-row], half2 col pairs
__device__ float   g_mu[T_STEPS];
__device__ float   g_part[NCTA];

// ---------------------------------------------------------------------------
// Prep: per-step layer-1 constants (0.5-scaled, fragment-packed) + mu(t)
// ---------------------------------------------------------------------------
__global__ void prep_kernel(const float* __restrict__ X_seq,
                            const float* __restrict__ a,
                            const float* __restrict__ b0p,
                            const float* __restrict__ b1p,
                            const float* __restrict__ b2p,
                            const float* __restrict__ Sp,
                            const float* __restrict__ dW1,
                            const float* __restrict__ db1,
                            const float* __restrict__ gW1,
                            const float* __restrict__ gb1,
                            const int*   __restrict__ i0p)
{
    int t = blockIdx.x;            // 0..1023
    int j = threadIdx.x;           // 0..127
    int i0 = *i0p;
    float tk = (float)(i0 + t);
    const float* x = X_seq + (size_t)(i0 + t) * 3;
    float x0 = x[0], x1 = x[1], x2 = x[2];

    int net = j >> 6, s = j & 63;
    const float* W1 = net ? gW1 : dW1;   // [5][64] row-major; row0 = z coeff
    const float* B1 = net ? gb1 : db1;

    if (s < 16) {
        int kt = s >> 2, tg = s & 3;
        int pl = kt * 8 + tg, ph = pl + 4;       // half2 pair indices
        float v[4];
        int cols[4] = {2 * pl, 2 * pl + 1, 2 * ph, 2 * ph + 1};
#pragma unroll
        for (int q = 0; q < 4; q++) {
            int c = cols[q];
            v[q] = B1[c] + x0 * W1[64 + c] + x1 * W1[128 + c]
                         + x2 * W1[192 + c] + tk * W1[256 + c];
        }
        __half2 lo = __floats2half2_rn(0.5f * v[0], 0.5f * v[1]);
        __half2 hi = __floats2half2_rn(0.5f * v[2], 0.5f * v[3]);
        uint2 out;
        out.x = *reinterpret_cast<unsigned*>(&lo);
        out.y = *reinterpret_cast<unsigned*>(&hi);
        g_c1p[(net * T_STEPS + t) * 16 + s] = out;
    }
    if (s >= 32 && s < 64 && t == 0) {
        int p = s - 32;                           // pair index 0..31
        g_w05h[net * 32 + p] = __floats2half2_rn(0.5f * W1[2 * p],
                                                 0.5f * W1[2 * p + 1]);
    }
    if (j == 0) {
        float w = 6.283185307179586f * tk / (*Sp);
        g_mu[t] = x0 * a[0] + x1 * a[1] + x2 * a[2]
                + (*b0p) + (*b1p) * sinf(w) + (*b2p) * cosf(w);
    }
}

// ---------------------------------------------------------------------------
// helpers
// ---------------------------------------------------------------------------
__device__ __forceinline__ unsigned silu2h(__half2 m) {
    unsigned mi = *reinterpret_cast<unsigned*>(&m), ti;
    asm("tanh.approx.f16x2 %0, %1;\n" : "=r"(ti) : "r"(mi));
    __half2 tt = *reinterpret_cast<__half2*>(&ti);
    __half2 h = __hfma2(m, tt, m);
    return *reinterpret_cast<unsigned*>(&h);
}

__device__ __forceinline__ void mma16816_f(float& c0, float& c1, float& c2, float& c3,
                                           unsigned a0, unsigned a1, unsigned a2, unsigned a3,
                                           unsigned b0, unsigned b1)
{
    asm volatile(
        "mma.sync.aligned.m16n8k16.row.col.f32.f16.f16.f32 "
        "{%0,%1,%2,%3}, {%4,%5,%6,%7}, {%8,%9}, {%0,%1,%2,%3};\n"
        : "+f"(c0), "+f"(c1), "+f"(c2), "+f"(c3)
        : "r"(a0), "r"(a1), "r"(a2), "r"(a3), "r"(b0), "r"(b1));
}

__device__ __forceinline__ void mma16816_h(unsigned& d0, unsigned& d1,
                                           unsigned a0, unsigned a1, unsigned a2, unsigned a3,
                                           unsigned b0, unsigned b1)
{
    asm volatile(
        "mma.sync.aligned.m16n8k16.row.col.f16.f16.f16.f16 "
        "{%0,%1}, {%2,%3,%4,%5}, {%6,%7}, {%0,%1};\n"
        : "+r"(d0), "+r"(d1)
        : "r"(a0), "r"(a1), "r"(a2), "r"(a3), "r"(b0), "r"(b1));
}

// ---------------------------------------------------------------------------
// Main: 148 CTAs x 7 warp-pairs; each pair = 32 paths, one warp per net.
// ---------------------------------------------------------------------------
__global__ void __launch_bounds__(TPB, 1) main_kernel(
    const float* __restrict__ y_seq,
    const float* __restrict__ kappap,
    const float* __restrict__ dW2, const float* __restrict__ db2,
    const float* __restrict__ dW3, const float* __restrict__ db3,
    const float* __restrict__ gW2, const float* __restrict__ gb2,
    const float* __restrict__ gW3, const float* __restrict__ gb3,
    const float* __restrict__ xi,
    const int*   __restrict__ i0p)
{
    // W2^T b-fragments packed for LDS.128:
    //   Bp[net][(ktp*4+kt)*32 + lane] = uint4{ ntl0: (klo,khi), ntl1: (klo,khi) }
    // where lane=(g<<2)|tg, n_ntl = ktp*16 + ntl*8 + g, k0 = kt*16 + 2*tg.
    __shared__ uint4 Bp[2][16 * 32];
    __shared__ float ex[2][NPAIRS][2][32];   // [phase][pair][net][path-lane]
    __shared__ float red[2 * NPAIRS];

    int tid  = threadIdx.x;
    int lane = tid & 31, warp = tid >> 5;
    int pair = warp >> 1, net = warp & 1;
    int g = lane >> 2, tg = lane & 3;

    // fill Bp (both nets, all threads)
    {
        const float* W2n[2] = { dW2, gW2 };
        for (int e = tid; e < 2 * 16 * 32; e += TPB) {
            int nn  = e >> 9;
            int rem = e & 511;
            int idx = rem >> 5;          // ktp*4+kt
            int ll  = rem & 31;
            int gg = ll >> 2, tq = ll & 3;
            int ktp = idx >> 2, kt = idx & 3;
            int n0 = ktp * 16 + gg, n1 = ktp * 16 + 8 + gg;
            int k0 = kt * 16 + 2 * tq;
            const float* W2 = W2n[nn];
            __half2 x0 = __floats2half2_rn(W2[k0 * 64 + n0],       W2[(k0 + 1) * 64 + n0]);
            __half2 y0 = __floats2half2_rn(W2[(k0 + 8) * 64 + n0], W2[(k0 + 9) * 64 + n0]);
            __half2 x1 = __floats2half2_rn(W2[k0 * 64 + n1],       W2[(k0 + 1) * 64 + n1]);
            __half2 y1 = __floats2half2_rn(W2[(k0 + 8) * 64 + n1], W2[(k0 + 9) * 64 + n1]);
            uint4 v;
            v.x = *reinterpret_cast<unsigned*>(&x0);
            v.y = *reinterpret_cast<unsigned*>(&y0);
            v.z = *reinterpret_cast<unsigned*>(&x1);
            v.w = *reinterpret_cast<unsigned*>(&y1);
            Bp[nn][idx * 32 + ll] = v;
        }
    }
    __syncthreads();

    int   i0    = *i0p;
    float kappa = *kappap;

    // this warp's net-specific constants
    const float* W3p = net ? gW3 : dW3;
    const float* B2p = net ? gb2 : db2;
    float b3 = net ? gb3[0] : db3[0];

    __half2 wh[4][2];
#pragma unroll
    for (int kt = 0; kt < 4; kt++) {
        wh[kt][0] = __ldg(g_w05h + net * 32 + kt * 8 + tg);
        wh[kt][1] = __ldg(g_w05h + net * 32 + kt * 8 + tg + 4);
    }
    __half2 hb2[8];
#pragma unroll
    for (int nt = 0; nt < 8; nt++) {
        int c = nt * 8 + 2 * tg;
        hb2[nt] = __floats2half2_rn(0.5f * B2p[c], 0.5f * B2p[c + 1]);
    }
    unsigned bw3[4][2];
#pragma unroll
    for (int kp = 0; kp < 4; kp++) {
        if (g == 0) {
            int k0 = kp * 16 + 2 * tg;
            __half2 l = __floats2half2_rn(W3p[k0],     W3p[k0 + 1]);
            __half2 h = __floats2half2_rn(W3p[k0 + 8], W3p[k0 + 9]);
            bw3[kp][0] = *reinterpret_cast<unsigned*>(&l);
            bw3[kp][1] = *reinterpret_cast<unsigned*>(&h);
        } else {
            bw3[kp][0] = 0u; bw3[kp][1] = 0u;
        }
    }

    // pair's global tile; lane owns path gp*32 + lane
    int gp = blockIdx.x * NPAIRS + pair;
    bool active = (gp < NMC / NPATH_W);
    float ssum = 0.0f;

    if (active) {
        float y0 = fminf(fmaxf(y_seq[i0 - 1], 1e-4f), 1.0f - 1e-4f);
        float z  = logf(y0 / (1.0f - y0));
        const float* yobs = y_seq + i0;
        const float* xip  = xi + gp * NPATH_W + lane;
        const __half2 h05 = __floats2half2_rn(0.5f, 0.5f);
        int src = 4 * (lane & 7);
        const uint4* BpN = Bp[net];
        const uint2* c1base = g_c1p + (size_t)net * T_STEPS * 16;

        for (int t = 0; t < T_STEPS; t++) {
            // z broadcast for the 2 m-tiles (rows: mt*16 + g, mt*16 + 8 + g)
            __half2 zh[2][2];
#pragma unroll
            for (int mt = 0; mt < 2; mt++) {
                zh[mt][0] = __half2half2(__float2half(
                                __shfl_sync(0xffffffffu, z, mt * 16 + g)));
                zh[mt][1] = __half2half2(__float2half(
                                __shfl_sync(0xffffffffu, z, mt * 16 + 8 + g)));
            }

            float xik = __ldg(xip + (size_t)t * NMC);
            float mu  = g_mu[t];

            // ---- layer-1: A fragments for both m-tiles ----
            const uint2* c1t = c1base + t * 16;
            unsigned A[2][4][4];
#pragma unroll
            for (int kt = 0; kt < 4; kt++) {
                uint2 cc = __ldg(c1t + kt * 4 + tg);
                __half2 clo = *reinterpret_cast<__half2*>(&cc.x);
                __half2 chi = *reinterpret_cast<__half2*>(&cc.y);
                __half2 wlo = wh[kt][0], whi = wh[kt][1];
#pragma unroll
                for (int mt = 0; mt < 2; mt++) {
                    A[mt][kt][0] = silu2h(__hfma2(zh[mt][0], wlo, clo));
                    A[mt][kt][1] = silu2h(__hfma2(zh[mt][1], wlo, clo));
                    A[mt][kt][2] = silu2h(__hfma2(zh[mt][0], whi, chi));
                    A[mt][kt][3] = silu2h(__hfma2(zh[mt][1], whi, chi));
                }
            }

            // layer-3 accumulators, bias on col0 (tg==0 lanes)
            float d[2][4];
#pragma unroll
            for (int mt = 0; mt < 2; mt++) {
                d[mt][0] = (tg == 0) ? b3 : 0.0f; d[mt][1] = 0.0f;
                d[mt][2] = (tg == 0) ? b3 : 0.0f; d[mt][3] = 0.0f;
            }

            // ---- layer-2 (f16 accum) + fused layer-3 ----
#pragma unroll
            for (int ktp = 0; ktp < 4; ktp++) {
                unsigned acc[2][2][2];
#pragma unroll
                for (int mt = 0; mt < 2; mt++) {
                    acc[mt][0][0] = acc[mt][0][1] = 0u;
                    acc[mt][1][0] = acc[mt][1][1] = 0u;
                }
#pragma unroll
                for (int kt = 0; kt < 4; kt++) {
                    uint4 b = BpN[(ktp * 4 + kt) * 32 + lane];
#pragma unroll
                    for (int mt = 0; mt < 2; mt++) {
                        mma16816_h(acc[mt][0][0], acc[mt][0][1],
                                   A[mt][kt][0], A[mt][kt][1], A[mt][kt][2], A[mt][kt][3],
                                   b.x, b.y);
                        mma16816_h(acc[mt][1][0], acc[mt][1][1],
                                   A[mt][kt][0], A[mt][kt][1], A[mt][kt][2], A[mt][kt][3],
                                   b.z, b.w);
                    }
                }
                __half2 bb0 = hb2[2 * ktp], bb1 = hb2[2 * ktp + 1];
#pragma unroll
                for (int mt = 0; mt < 2; mt++) {
                    __half2 a00 = *reinterpret_cast<__half2*>(&acc[mt][0][0]);
                    __half2 a01 = *reinterpret_cast<__half2*>(&acc[mt][0][1]);
                    __half2 a10 = *reinterpret_cast<__half2*>(&acc[mt][1][0]);
                    __half2 a11 = *reinterpret_cast<__half2*>(&acc[mt][1][1]);
                    unsigned e0 = silu2h(__hfma2(a00, h05, bb0));
                    unsigned e1 = silu2h(__hfma2(a01, h05, bb0));
                    unsigned e2 = silu2h(__hfma2(a10, h05, bb1));
                    unsigned e3 = silu2h(__hfma2(a11, h05, bb1));
                    mma16816_f(d[mt][0], d[mt][1], d[mt][2], d[mt][3],
                               e0, e1, e2, e3, bw3[ktp][0], bw3[ktp][1]);
                }
            }

            // gather col0 results: path lane -> its own net output
            float v00 = __shfl_sync(0xffffffffu, d[0][0], src);
            float v01 = __shfl_sync(0xffffffffu, d[0][2], src);
            float v10 = __shfl_sync(0xffffffffu, d[1][0], src);
            float v11 = __shfl_sync(0xffffffffu, d[1][2], src);
            float myval = (lane & 16) ? ((lane & 8) ? v11 : v10)
                                      : ((lane & 8) ? v01 : v00);

            // net-specific transform, then pair exchange
            float pub;
            if (net == 0) {
                pub = myval;                                   // f_res
            } else {
                pub = fmaxf(myval, 0.0f)
                    + log1pf(__expf(-fabsf(myval))) + 1e-6f;   // g (softplus)
            }
            int ph = t & 1;
            ex[ph][pair][net][lane] = pub;
            asm volatile("bar.sync %0, 64;" :: "r"(1 + pair) : "memory");
            float other = ex[ph][pair][net ^ 1][lane];

            float fval = net ? other : pub;
            float gval = net ? pub : other;
            z = z + kappa * (mu - z) + fval + gval * xik;      // identical in both warps

            if (net == 0) {
                float U  = __fdividef(1.0f, 1.0f + __expf(-z));
                float dy = yobs[t] - U;
                ssum = fmaf(dy, dy, ssum);
            }
        }
    }

    // only f-warps carry loss; reduce CTA-wide
    if (net != 0) ssum = 0.0f;
#pragma unroll
    for (int o = 16; o; o >>= 1) ssum += __shfl_xor_sync(0xffffffffu, ssum, o);
    if (lane == 0) red[warp] = ssum;
    __syncthreads();
    if (warp == 0) {
        float s = (lane < 2 * NPAIRS) ? red[lane] : 0.0f;
#pragma unroll
        for (int o = 8; o; o >>= 1) s += __shfl_xor_sync(0xffffffffu, s, o);
        if (lane == 0) g_part[blockIdx.x] = s;
    }
}

// ---------------------------------------------------------------------------
// Finalize: reduce 148 partials, apply 0.5/sigma^2 and log-sigma terms
// ---------------------------------------------------------------------------
__global__ void fin_kernel(const float* __restrict__ lsop, float* __restrict__ out)
{
    int lane = threadIdx.x;                // 32 threads
    float s = 0.0f;
    for (int i = lane; i < NCTA; i += 32) s += g_part[i];
#pragma unroll
    for (int o = 16; o; o >>= 1) s += __shfl_xor_sync(0xffffffffu, s, o);
    if (lane == 0) {
        float lso = *lsop;
        float sig = expf(lso) + 1e-8f;
        out[0] = 0.5f * s / ((float)T_STEPS * (float)NMC) / (sig * sig) + lso;
    }
}

// ---------------------------------------------------------------------------
extern "C" void kernel_launch(void* const* d_in, const int* in_sizes, int n_in,
                              void* d_out, int out_size)
{
    const float* X_seq = (const float*)d_in[0];
    const float* y_seq = (const float*)d_in[1];
    const float* kappa = (const float*)d_in[2];
    const float* a     = (const float*)d_in[3];
    const float* b0    = (const float*)d_in[4];
    const float* b1    = (const float*)d_in[5];
    const float* b2    = (const float*)d_in[6];
    const float* S     = (const float*)d_in[7];
    const float* lso   = (const float*)d_in[8];
    const float* dW1   = (const float*)d_in[9];
    const float* db1   = (const float*)d_in[10];
    const float* dW2   = (const float*)d_in[11];
    const float* db2   = (const float*)d_in[12];
    const float* dW3   = (const float*)d_in[13];
    const float* db3   = (const float*)d_in[14];
    const float* gW1   = (const float*)d_in[15];
    const float* gb1   = (const float*)d_in[16];
    const float* gW2   = (const float*)d_in[17];
    const float* gb2   = (const float*)d_in[18];
    const float* gW3   = (const float*)d_in[19];
    const float* gb3   = (const float*)d_in[20];
    const float* xi    = (const float*)d_in[21];
    const int*   i0    = (const int*)d_in[22];

    prep_kernel<<<T_STEPS, 128>>>(X_seq, a, b0, b1, b2, S, dW1, db1, gW1, gb1, i0);
    main_kernel<<<NCTA, TPB>>>(y_seq, kappa, dW2, db2, dW3, db3,
                               gW2, gb2, gW3, gb3, xi, i0);
    fin_kernel<<<1, 32>>>(lso, (float*)d_out);
}

// round 6
// speedup vs baseline: 1.4735x; 1.4735x over previous
#include <cuda_runtime.h>
#include <cuda_fp16.h>
#include <math.h>

#define T_STEPS 1024
#define NMC     32768
#define NCTA    148
#define NWARPS  14
#define TPB     (NWARPS * 32)   // 448
#define NGROUPS (NMC / 16)      // 2048 path-groups of 16

// ---- scratch (__device__ globals) -------------------------------------------
// layer-1 per-step consts, 0.5-scaled, packed per (net,t,kt,tg):
//   uint2{ half2 pair(kt*8+tg), half2 pair(kt*8+tg+4) }
__device__ uint2   g_c1p[2 * T_STEPS * 16];
__device__ __half2 g_w05h[2 * 32];           // 0.5 * W1[z-row], half2 col pairs
__device__ float   g_mu[T_STEPS];
__device__ float   g_part[NCTA];

// ---------------------------------------------------------------------------
// Prep: per-step layer-1 constants (0.5-scaled, fragment-packed) + mu(t)
// ---------------------------------------------------------------------------
__global__ void prep_kernel(const float* __restrict__ X_seq,
                            const float* __restrict__ a,
                            const float* __restrict__ b0p,
                            const float* __restrict__ b1p,
                            const float* __restrict__ b2p,
                            const float* __restrict__ Sp,
                            const float* __restrict__ dW1,
                            const float* __restrict__ db1,
                            const float* __restrict__ gW1,
                            const float* __restrict__ gb1,
                            const int*   __restrict__ i0p)
{
    int t = blockIdx.x;            // 0..1023
    int j = threadIdx.x;           // 0..127
    int i0 = *i0p;
    float tk = (float)(i0 + t);
    const float* x = X_seq + (size_t)(i0 + t) * 3;
    float x0 = x[0], x1 = x[1], x2 = x[2];

    int net = j >> 6, s = j & 63;
    const float* W1 = net ? gW1 : dW1;   // [5][64] row-major; row0 = z coeff
    const float* B1 = net ? gb1 : db1;

    if (s < 16) {
        int kt = s >> 2, tg = s & 3;
        int pl = kt * 8 + tg, ph = pl + 4;       // half2 pair indices
        float v[4];
        int cols[4] = {2 * pl, 2 * pl + 1, 2 * ph, 2 * ph + 1};
#pragma unroll
        for (int q = 0; q < 4; q++) {
            int c = cols[q];
            v[q] = B1[c] + x0 * W1[64 + c] + x1 * W1[128 + c]
                         + x2 * W1[192 + c] + tk * W1[256 + c];
        }
        __half2 lo = __floats2half2_rn(0.5f * v[0], 0.5f * v[1]);
        __half2 hi = __floats2half2_rn(0.5f * v[2], 0.5f * v[3]);
        uint2 out;
        out.x = *reinterpret_cast<unsigned*>(&lo);
        out.y = *reinterpret_cast<unsigned*>(&hi);
        g_c1p[(net * T_STEPS + t) * 16 + s] = out;
    }
    if (s >= 32 && s < 64 && t == 0) {
        int p = s - 32;                           // pair index 0..31
        g_w05h[net * 32 + p] = __floats2half2_rn(0.5f * W1[2 * p],
                                                 0.5f * W1[2 * p + 1]);
    }
    if (j == 0) {
        float w = 6.283185307179586f * tk / (*Sp);
        g_mu[t] = x0 * a[0] + x1 * a[1] + x2 * a[2]
                + (*b0p) + (*b1p) * sinf(w) + (*b2p) * cosf(w);
    }
}

// ---------------------------------------------------------------------------
// helpers
// ---------------------------------------------------------------------------
__device__ __forceinline__ unsigned silu2h(__half2 m) {
    unsigned mi = *reinterpret_cast<unsigned*>(&m), ti;
    asm("tanh.approx.f16x2 %0, %1;\n" : "=r"(ti) : "r"(mi));
    __half2 tt = *reinterpret_cast<__half2*>(&ti);
    __half2 h = __hfma2(m, tt, m);
    return *reinterpret_cast<unsigned*>(&h);
}

__device__ __forceinline__ void mma16816_f(float& c0, float& c1, float& c2, float& c3,
                                           unsigned a0, unsigned a1, unsigned a2, unsigned a3,
                                           unsigned b0, unsigned b1)
{
    asm volatile(
        "mma.sync.aligned.m16n8k16.row.col.f32.f16.f16.f32 "
        "{%0,%1,%2,%3}, {%4,%5,%6,%7}, {%8,%9}, {%0,%1,%2,%3};\n"
        : "+f"(c0), "+f"(c1), "+f"(c2), "+f"(c3)
        : "r"(a0), "r"(a1), "r"(a2), "r"(a3), "r"(b0), "r"(b1));
}

__device__ __forceinline__ void mma16816_h(unsigned& d0, unsigned& d1,
                                           unsigned a0, unsigned a1, unsigned a2, unsigned a3,
                                           unsigned b0, unsigned b1)
{
    asm volatile(
        "mma.sync.aligned.m16n8k16.row.col.f16.f16.f16.f16 "
        "{%0,%1}, {%2,%3,%4,%5}, {%6,%7}, {%0,%1};\n"
        : "+r"(d0), "+r"(d1)
        : "r"(a0), "r"(a1), "r"(a2), "r"(a3), "r"(b0), "r"(b1));
}

// ---------------------------------------------------------------------------
// Main: 148 CTAs x 14 warps x 16 paths, full 1024-step scan in-kernel.
// Warps fully independent (no per-step sync).
// ---------------------------------------------------------------------------
__global__ void __launch_bounds__(TPB, 1) main_kernel(
    const float* __restrict__ y_seq,
    const float* __restrict__ kappap,
    const float* __restrict__ dW2, const float* __restrict__ db2,
    const float* __restrict__ dW3, const float* __restrict__ db3,
    const float* __restrict__ gW2, const float* __restrict__ gb2,
    const float* __restrict__ gW3, const float* __restrict__ gb3,
    const float* __restrict__ xi,
    const int*   __restrict__ i0p)
{
    // W2^T b-fragments packed for LDS.128:
    //   Bp[net][(ktp*4+kt)*32 + lane] = uint4{ ntl0:(klo,khi), ntl1:(klo,khi) }
    // where lane=(g<<2)|tg, n(ntl) = ktp*16 + ntl*8 + g, k0 = kt*16 + 2*tg.
    __shared__ uint4 Bp[2][16 * 32];
    __shared__ float red[NWARPS];

    int tid  = threadIdx.x;
    int lane = tid & 31, warp = tid >> 5;
    int g = lane >> 2, tg = lane & 3;

    // fill Bp (both nets, all threads)
    {
        const float* W2n[2] = { dW2, gW2 };
        for (int e = tid; e < 2 * 16 * 32; e += TPB) {
            int nn  = e >> 9;
            int rem = e & 511;
            int idx = rem >> 5;          // ktp*4+kt
            int ll  = rem & 31;
            int gg = ll >> 2, tq = ll & 3;
            int ktp = idx >> 2, kt = idx & 3;
            int n0 = ktp * 16 + gg, n1 = ktp * 16 + 8 + gg;
            int k0 = kt * 16 + 2 * tq;
            const float* W2 = W2n[nn];
            __half2 x0 = __floats2half2_rn(W2[k0 * 64 + n0],       W2[(k0 + 1) * 64 + n0]);
            __half2 y0 = __floats2half2_rn(W2[(k0 + 8) * 64 + n0], W2[(k0 + 9) * 64 + n0]);
            __half2 x1 = __floats2half2_rn(W2[k0 * 64 + n1],       W2[(k0 + 1) * 64 + n1]);
            __half2 y1 = __floats2half2_rn(W2[(k0 + 8) * 64 + n1], W2[(k0 + 9) * 64 + n1]);
            uint4 v;
            v.x = *reinterpret_cast<unsigned*>(&x0);
            v.y = *reinterpret_cast<unsigned*>(&y0);
            v.z = *reinterpret_cast<unsigned*>(&x1);
            v.w = *reinterpret_cast<unsigned*>(&y1);
            Bp[nn][idx * 32 + ll] = v;
        }
    }
    __syncthreads();

    int   i0    = *i0p;
    float kappa = *kappap;

    // 0.5-scaled layer-1 z-weights (half2), per-lane column pairs
    __half2 wh[2][4][2];
#pragma unroll
    for (int net = 0; net < 2; net++)
#pragma unroll
        for (int kt = 0; kt < 4; kt++) {
            wh[net][kt][0] = __ldg(g_w05h + net * 32 + kt * 8 + tg);
            wh[net][kt][1] = __ldg(g_w05h + net * 32 + kt * 8 + tg + 4);
        }

    // 0.5*b2 at this lane's output column pairs (half2)
    __half2 hb2[2][8];
#pragma unroll
    for (int nt = 0; nt < 8; nt++) {
        int c = nt * 8 + 2 * tg;
        hb2[0][nt] = __floats2half2_rn(0.5f * db2[c], 0.5f * db2[c + 1]);
        hb2[1][nt] = __floats2half2_rn(0.5f * gb2[c], 0.5f * gb2[c + 1]);
    }

    // layer-3 weights as one-hot-column B fragments (col 0 <=> g==0 lanes)
    unsigned bw3[2][4][2];
#pragma unroll
    for (int net = 0; net < 2; net++) {
        const float* W3 = net ? gW3 : dW3;       // [64][1]
#pragma unroll
        for (int kp = 0; kp < 4; kp++) {
            if (g == 0) {
                int k0 = kp * 16 + 2 * tg;
                __half2 l = __floats2half2_rn(W3[k0],     W3[k0 + 1]);
                __half2 h = __floats2half2_rn(W3[k0 + 8], W3[k0 + 9]);
                bw3[net][kp][0] = *reinterpret_cast<unsigned*>(&l);
                bw3[net][kp][1] = *reinterpret_cast<unsigned*>(&h);
            } else {
                bw3[net][kp][0] = 0u; bw3[net][kp][1] = 0u;
            }
        }
    }
    float b3[2] = { db3[0], gb3[0] };

    // warp owns 16 paths; lane p<16 owns path p (lanes 16-31 mirror lanes 0-15)
    int wg = blockIdx.x * NWARPS + warp;        // global warp-slot
    bool active = (wg < NGROUPS);
    float ssum = 0.0f;

    if (active) {
        float y0 = fminf(fmaxf(y_seq[i0 - 1], 1e-4f), 1.0f - 1e-4f);
        float z  = logf(y0 / (1.0f - y0));
        const float* yobs = y_seq + i0;
        int pglob = wg * 16 + (lane & 15);
        const __half2 h05 = __floats2half2_rn(0.5f, 0.5f);
        int src = 4 * (lane & 7);      // layer-3 result gather source lane

        for (int t = 0; t < T_STEPS; t++) {
            // broadcast z of A-tile rows g and g+8 (path p lives on lane p)
            float za = __shfl_sync(0xffffffffu, z, g);
            float zb = __shfl_sync(0xffffffffu, z, g + 8);
            __half2 zh0 = __half2half2(__float2half(za));
            __half2 zh1 = __half2half2(__float2half(zb));

            float xik = __ldg(xi + (size_t)t * NMC + pglob);
            float mu  = g_mu[t];
            float fg[2];

#pragma unroll
            for (int net = 0; net < 2; net++) {
                const uint2* c1t = g_c1p + (size_t)(net * T_STEPS + t) * 16;

                // ---- layer-1: h1 built directly as A fragments ----
                unsigned A[4][4];   // [kt][reg]
#pragma unroll
                for (int kt = 0; kt < 4; kt++) {
                    uint2 cc = __ldg(c1t + kt * 4 + tg);
                    __half2 clo = *reinterpret_cast<__half2*>(&cc.x);
                    __half2 chi = *reinterpret_cast<__half2*>(&cc.y);
                    __half2 wlo = wh[net][kt][0], whi = wh[net][kt][1];
                    A[kt][0] = silu2h(__hfma2(zh0, wlo, clo));
                    A[kt][1] = silu2h(__hfma2(zh1, wlo, clo));
                    A[kt][2] = silu2h(__hfma2(zh0, whi, chi));
                    A[kt][3] = silu2h(__hfma2(zh1, whi, chi));
                }

                // layer-3 accumulators, bias folded in (col 0 on tg==0 lanes)
                float d0 = (tg == 0) ? b3[net] : 0.0f, d1 = 0.0f;
                float d2 = (tg == 0) ? b3[net] : 0.0f, d3 = 0.0f;

                // ---- layer-2 GEMM (f16 accum) + fused layer-3 MMA ----
#pragma unroll
                for (int ktp = 0; ktp < 4; ktp++) {
                    unsigned acc[2][2];   // [ntl][reg] packed half2
                    acc[0][0] = acc[0][1] = acc[1][0] = acc[1][1] = 0u;
#pragma unroll
                    for (int kt = 0; kt < 4; kt++) {
                        uint4 b = Bp[net][(ktp * 4 + kt) * 32 + lane];
                        mma16816_h(acc[0][0], acc[0][1],
                                   A[kt][0], A[kt][1], A[kt][2], A[kt][3],
                                   b.x, b.y);
                        mma16816_h(acc[1][0], acc[1][1],
                                   A[kt][0], A[kt][1], A[kt][2], A[kt][3],
                                   b.z, b.w);
                    }
                    // epilogue: h2 = silu(acc+b2) straight into layer-3 A-frag
                    __half2 bb0 = hb2[net][2 * ktp], bb1 = hb2[net][2 * ktp + 1];
                    __half2 a00 = *reinterpret_cast<__half2*>(&acc[0][0]);
                    __half2 a01 = *reinterpret_cast<__half2*>(&acc[0][1]);
                    __half2 a10 = *reinterpret_cast<__half2*>(&acc[1][0]);
                    __half2 a11 = *reinterpret_cast<__half2*>(&acc[1][1]);
                    unsigned e0 = silu2h(__hfma2(a00, h05, bb0));  // row g,   k lo
                    unsigned e1 = silu2h(__hfma2(a01, h05, bb0));  // row g+8, k lo
                    unsigned e2 = silu2h(__hfma2(a10, h05, bb1));  // row g,   k hi
                    unsigned e3 = silu2h(__hfma2(a11, h05, bb1));  // row g+8, k hi
                    mma16816_f(d0, d1, d2, d3,
                               e0, e1, e2, e3, bw3[net][ktp][0], bw3[net][ktp][1]);
                }

                // result col0: row g on (tg==0).d0, row g+8 on (tg==0).d2
                float v0 = __shfl_sync(0xffffffffu, d0, src);
                float v2 = __shfl_sync(0xffffffffu, d2, src);
                fg[net] = (lane & 8) ? v2 : v0;
            }

            // state update (dt = 1, sqrt_dt = 1)
            float graw = fg[1];
            float gval = fmaxf(graw, 0.0f)
                       + __logf(1.0f + __expf(-fabsf(graw))) + 1e-6f;
            z = z + kappa * (mu - z) + fg[0] + gval * xik;

            float U  = __fdividef(1.0f, 1.0f + __expf(-z));   // fp32 sigmoid
            float dy = yobs[t] - U;
            ssum = fmaf(dy, dy, ssum);
        }
    }

    // lanes 16-31 are mirrors: drop their duplicate sums
    if (lane >= 16) ssum = 0.0f;

    // deterministic reduction: warp -> CTA -> g_part
#pragma unroll
    for (int o = 16; o; o >>= 1) ssum += __shfl_xor_sync(0xffffffffu, ssum, o);
    if (lane == 0) red[warp] = ssum;
    __syncthreads();
    if (warp == 0) {
        float s = (lane < NWARPS) ? red[lane] : 0.0f;
#pragma unroll
        for (int o = 8; o; o >>= 1) s += __shfl_xor_sync(0xffffffffu, s, o);
        if (lane == 0) g_part[blockIdx.x] = s;
    }
}

// ---------------------------------------------------------------------------
// Finalize: reduce 148 partials, apply 0.5/sigma^2 and log-sigma terms
// ---------------------------------------------------------------------------
__global__ void fin_kernel(const float* __restrict__ lsop, float* __restrict__ out)
{
    int lane = threadIdx.x;                // 32 threads
    float s = 0.0f;
    for (int i = lane; i < NCTA; i += 32) s += g_part[i];
#pragma unroll
    for (int o = 16; o; o >>= 1) s += __shfl_xor_sync(0xffffffffu, s, o);
    if (lane == 0) {
        float lso = *lsop;
        float sig = expf(lso) + 1e-8f;
        out[0] = 0.5f * s / ((float)T_STEPS * (float)NMC) / (sig * sig) + lso;
    }
}

// ---------------------------------------------------------------------------
extern "C" void kernel_launch(void* const* d_in, const int* in_sizes, int n_in,
                              void* d_out, int out_size)
{
    const float* X_seq = (const float*)d_in[0];
    const float* y_seq = (const float*)d_in[1];
    const float* kappa = (const float*)d_in[2];
    const float* a     = (const float*)d_in[3];
    const float* b0    = (const float*)d_in[4];
    const float* b1    = (const float*)d_in[5];
    const float* b2    = (const float*)d_in[6];
    const float* S     = (const float*)d_in[7];
    const float* lso   = (const float*)d_in[8];
    const float* dW1   = (const float*)d_in[9];
    const float* db1   = (const float*)d_in[10];
    const float* dW2   = (const float*)d_in[11];
    const float* db2   = (const float*)d_in[12];
    const float* dW3   = (const float*)d_in[13];
    const float* db3   = (const float*)d_in[14];
    const float* gW1   = (const float*)d_in[15];
    const float* gb1   = (const float*)d_in[16];
    const float* gW2   = (const float*)d_in[17];
    const float* gb2   = (const float*)d_in[18];
    const float* gW3   = (const float*)d_in[19];
    const float* gb3   = (const float*)d_in[20];
    const float* xi    = (const float*)d_in[21];
    const int*   i0    = (const int*)d_in[22];

    prep_kernel<<<T_STEPS, 128>>>(X_seq, a, b0, b1, b2, S, dW1, db1, gW1, gb1, i0);
    main_kernel<<<NCTA, TPB>>>(y_seq, kappa, dW2, db2, dW3, db3,
                               gW2, gb2, gW3, gb3, xi, i0);
    fin_kernel<<<1, 32>>>(lso, (float*)d_out);
}

// round 7
// speedup vs baseline: 1.5109x; 1.0254x over previous
#include <cuda_runtime.h>
#include <cuda_fp16.h>
#include <math.h>

#define T_STEPS 1024
#define NMC     32768
#define NCTA    148
#define NWARPS  14
#define TPB     (NWARPS * 32)   // 448
#define NGROUPS (NMC / 16)      // 2048 path-groups of 16

// ---- scratch (__device__ globals) -------------------------------------------
// layer-1 per-step consts, 0.5-scaled, packed per (net,t,kt,tg):
//   uint2{ half2 pair(kt*8+tg), half2 pair(kt*8+tg+4) }
__device__ uint2   g_c1p[2 * T_STEPS * 16];
__device__ __half2 g_w05h[2 * 32];           // 0.5 * W1[z-row], half2 col pairs
__device__ float   g_mu[T_STEPS];
__device__ float   g_part[NCTA];

// ---------------------------------------------------------------------------
// Prep: per-step layer-1 constants (0.5-scaled, fragment-packed) + mu(t)
// ---------------------------------------------------------------------------
__global__ void prep_kernel(const float* __restrict__ X_seq,
                            const float* __restrict__ a,
                            const float* __restrict__ b0p,
                            const float* __restrict__ b1p,
                            const float* __restrict__ b2p,
                            const float* __restrict__ Sp,
                            const float* __restrict__ dW1,
                            const float* __restrict__ db1,
                            const float* __restrict__ gW1,
                            const float* __restrict__ gb1,
                            const int*   __restrict__ i0p)
{
    int t = blockIdx.x;            // 0..1023
    int j = threadIdx.x;           // 0..127
    int i0 = *i0p;
    float tk = (float)(i0 + t);
    const float* x = X_seq + (size_t)(i0 + t) * 3;
    float x0 = x[0], x1 = x[1], x2 = x[2];

    int net = j >> 6, s = j & 63;
    const float* W1 = net ? gW1 : dW1;   // [5][64] row-major; row0 = z coeff
    const float* B1 = net ? gb1 : db1;

    if (s < 16) {
        int kt = s >> 2, tg = s & 3;
        int pl = kt * 8 + tg, ph = pl + 4;       // half2 pair indices
        float v[4];
        int cols[4] = {2 * pl, 2 * pl + 1, 2 * ph, 2 * ph + 1};
#pragma unroll
        for (int q = 0; q < 4; q++) {
            int c = cols[q];
            v[q] = B1[c] + x0 * W1[64 + c] + x1 * W1[128 + c]
                         + x2 * W1[192 + c] + tk * W1[256 + c];
        }
        __half2 lo = __floats2half2_rn(0.5f * v[0], 0.5f * v[1]);
        __half2 hi = __floats2half2_rn(0.5f * v[2], 0.5f * v[3]);
        uint2 out;
        out.x = *reinterpret_cast<unsigned*>(&lo);
        out.y = *reinterpret_cast<unsigned*>(&hi);
        g_c1p[(net * T_STEPS + t) * 16 + s] = out;
    }
    if (s >= 32 && s < 64 && t == 0) {
        int p = s - 32;                           // pair index 0..31
        g_w05h[net * 32 + p] = __floats2half2_rn(0.5f * W1[2 * p],
                                                 0.5f * W1[2 * p + 1]);
    }
    if (j == 0) {
        float w = 6.283185307179586f * tk / (*Sp);
        g_mu[t] = x0 * a[0] + x1 * a[1] + x2 * a[2]
                + (*b0p) + (*b1p) * sinf(w) + (*b2p) * cosf(w);
    }
}

// ---------------------------------------------------------------------------
// helpers
// ---------------------------------------------------------------------------
__device__ __forceinline__ unsigned silu2h(__half2 m) {
    unsigned mi = *reinterpret_cast<unsigned*>(&m), ti;
    asm("tanh.approx.f16x2 %0, %1;\n" : "=r"(ti) : "r"(mi));
    __half2 tt = *reinterpret_cast<__half2*>(&ti);
    __half2 h = __hfma2(m, tt, m);
    return *reinterpret_cast<unsigned*>(&h);
}

__device__ __forceinline__ void mma16816_f(float& c0, float& c1, float& c2, float& c3,
                                           unsigned a0, unsigned a1, unsigned a2, unsigned a3,
                                           unsigned b0, unsigned b1)
{
    asm volatile(
        "mma.sync.aligned.m16n8k16.row.col.f32.f16.f16.f32 "
        "{%0,%1,%2,%3}, {%4,%5,%6,%7}, {%8,%9}, {%0,%1,%2,%3};\n"
        : "+f"(c0), "+f"(c1), "+f"(c2), "+f"(c3)
        : "r"(a0), "r"(a1), "r"(a2), "r"(a3), "r"(b0), "r"(b1));
}

__device__ __forceinline__ void mma16816_h(unsigned& d0, unsigned& d1,
                                           unsigned a0, unsigned a1, unsigned a2, unsigned a3,
                                           unsigned b0, unsigned b1)
{
    asm volatile(
        "mma.sync.aligned.m16n8k16.row.col.f16.f16.f16.f16 "
        "{%0,%1}, {%2,%3,%4,%5}, {%6,%7}, {%0,%1};\n"
        : "+r"(d0), "+r"(d1)
        : "r"(a0), "r"(a1), "r"(a2), "r"(a3), "r"(b0), "r"(b1));
}

// ---------------------------------------------------------------------------
// Main: 148 CTAs x 14 warps x 16 paths, full 1024-step scan in-kernel.
// Warps fully independent (no per-step sync).
// ---------------------------------------------------------------------------
__global__ void __launch_bounds__(TPB, 1) main_kernel(
    const float* __restrict__ y_seq,
    const float* __restrict__ kappap,
    const float* __restrict__ dW2, const float* __restrict__ db2,
    const float* __restrict__ dW3, const float* __restrict__ db3,
    const float* __restrict__ gW2, const float* __restrict__ gb2,
    const float* __restrict__ gW3, const float* __restrict__ gb3,
    const float* __restrict__ xi,
    const int*   __restrict__ i0p)
{
    // W2^T b-fragments packed for LDS.128:
    //   Bp[net][(ktp*4+kt)*32 + lane] = uint4{ ntl0:(klo,khi), ntl1:(klo,khi) }
    // where lane=(g<<2)|tg, n(ntl) = ktp*16 + ntl*8 + g, k0 = kt*16 + 2*tg.
    __shared__ uint4 Bp[2][16 * 32];
    __shared__ float red[NWARPS];

    int tid  = threadIdx.x;
    int lane = tid & 31, warp = tid >> 5;
    int g = lane >> 2, tg = lane & 3;

    // fill Bp (both nets, all threads)
    {
        const float* W2n[2] = { dW2, gW2 };
        for (int e = tid; e < 2 * 16 * 32; e += TPB) {
            int nn  = e >> 9;
            int rem = e & 511;
            int idx = rem >> 5;          // ktp*4+kt
            int ll  = rem & 31;
            int gg = ll >> 2, tq = ll & 3;
            int ktp = idx >> 2, kt = idx & 3;
            int n0 = ktp * 16 + gg, n1 = ktp * 16 + 8 + gg;
            int k0 = kt * 16 + 2 * tq;
            const float* W2 = W2n[nn];
            __half2 x0 = __floats2half2_rn(W2[k0 * 64 + n0],       W2[(k0 + 1) * 64 + n0]);
            __half2 y0 = __floats2half2_rn(W2[(k0 + 8) * 64 + n0], W2[(k0 + 9) * 64 + n0]);
            __half2 x1 = __floats2half2_rn(W2[k0 * 64 + n1],       W2[(k0 + 1) * 64 + n1]);
            __half2 y1 = __floats2half2_rn(W2[(k0 + 8) * 64 + n1], W2[(k0 + 9) * 64 + n1]);
            uint4 v;
            v.x = *reinterpret_cast<unsigned*>(&x0);
            v.y = *reinterpret_cast<unsigned*>(&y0);
            v.z = *reinterpret_cast<unsigned*>(&x1);
            v.w = *reinterpret_cast<unsigned*>(&y1);
            Bp[nn][idx * 32 + ll] = v;
        }
    }
    __syncthreads();

    int   i0    = *i0p;
    float kappa = *kappap;

    // 0.5-scaled layer-1 z-weights (half2), per-lane column pairs
    __half2 wh[2][4][2];
#pragma unroll
    for (int net = 0; net < 2; net++)
#pragma unroll
        for (int kt = 0; kt < 4; kt++) {
            wh[net][kt][0] = __ldg(g_w05h + net * 32 + kt * 8 + tg);
            wh[net][kt][1] = __ldg(g_w05h + net * 32 + kt * 8 + tg + 4);
        }

    // 0.5*b2 at this lane's output column pairs (half2)
    __half2 hb2[2][8];
#pragma unroll
    for (int nt = 0; nt < 8; nt++) {
        int c = nt * 8 + 2 * tg;
        hb2[0][nt] = __floats2half2_rn(0.5f * db2[c], 0.5f * db2[c + 1]);
        hb2[1][nt] = __floats2half2_rn(0.5f * gb2[c], 0.5f * gb2[c + 1]);
    }

    // layer-3 weights as one-hot-column B fragments (col 0 <=> g==0 lanes)
    unsigned bw3[2][4][2];
#pragma unroll
    for (int net = 0; net < 2; net++) {
        const float* W3 = net ? gW3 : dW3;       // [64][1]
#pragma unroll
        for (int kp = 0; kp < 4; kp++) {
            if (g == 0) {
                int k0 = kp * 16 + 2 * tg;
                __half2 l = __floats2half2_rn(W3[k0],     W3[k0 + 1]);
                __half2 h = __floats2half2_rn(W3[k0 + 8], W3[k0 + 9]);
                bw3[net][kp][0] = *reinterpret_cast<unsigned*>(&l);
                bw3[net][kp][1] = *reinterpret_cast<unsigned*>(&h);
            } else {
                bw3[net][kp][0] = 0u; bw3[net][kp][1] = 0u;
            }
        }
    }
    float b3[2] = { db3[0], gb3[0] };

    // warp owns 16 paths; lane p<16 owns path p (lanes 16-31 mirror lanes 0-15)
    int wg = blockIdx.x * NWARPS + warp;        // global warp-slot
    bool active = (wg < NGROUPS);
    float ssum = 0.0f;

    if (active) {
        float y0 = fminf(fmaxf(y_seq[i0 - 1], 1e-4f), 1.0f - 1e-4f);
        float z  = logf(y0 / (1.0f - y0));
        const float* yobs = y_seq + i0;
        int pglob = wg * 16 + (lane & 15);
        const __half2 h05 = __floats2half2_rn(0.5f, 0.5f);
        int src = 4 * (lane & 7);      // layer-3 result gather source lane

        // software-pipelined xi: prefetch step 0
        float xik_next = __ldg(xi + pglob);

        for (int t = 0; t < T_STEPS; t++) {
            // ---- issue ALL per-step loads first (overlap latency) ----
            float xik = xik_next;
            int tn = (t + 1 < T_STEPS) ? (t + 1) : t;
            xik_next = __ldg(xi + (size_t)tn * NMC + pglob);
            float mu  = g_mu[t];
            uint2 cc[2][4];
#pragma unroll
            for (int net = 0; net < 2; net++) {
                const uint2* c1t = g_c1p + (size_t)(net * T_STEPS + t) * 16;
#pragma unroll
                for (int kt = 0; kt < 4; kt++)
                    cc[net][kt] = __ldg(c1t + kt * 4 + tg);
            }
            float yt = __ldg(yobs + t) - 0.5f;

            // broadcast z of A-tile rows g and g+8 (path p lives on lane p)
            float za = __shfl_sync(0xffffffffu, z, g);
            float zb = __shfl_sync(0xffffffffu, z, g + 8);
            __half2 zh0 = __half2half2(__float2half(za));
            __half2 zh1 = __half2half2(__float2half(zb));

            float fg[2];

#pragma unroll
            for (int net = 0; net < 2; net++) {
                // ---- layer-1: h1 built directly as A fragments ----
                unsigned A[4][4];   // [kt][reg]
#pragma unroll
                for (int kt = 0; kt < 4; kt++) {
                    __half2 clo = *reinterpret_cast<__half2*>(&cc[net][kt].x);
                    __half2 chi = *reinterpret_cast<__half2*>(&cc[net][kt].y);
                    __half2 wlo = wh[net][kt][0], whi = wh[net][kt][1];
                    A[kt][0] = silu2h(__hfma2(zh0, wlo, clo));
                    A[kt][1] = silu2h(__hfma2(zh1, wlo, clo));
                    A[kt][2] = silu2h(__hfma2(zh0, whi, chi));
                    A[kt][3] = silu2h(__hfma2(zh1, whi, chi));
                }

                // layer-3: two accumulator sets (even/odd ktp) to halve the
                // serial MMA_f chain; bias folded into set a (col0, tg==0)
                float da0 = (tg == 0) ? b3[net] : 0.0f, da1 = 0.0f;
                float da2 = (tg == 0) ? b3[net] : 0.0f, da3 = 0.0f;
                float db0 = 0.0f, db1_ = 0.0f, db2_ = 0.0f, db3_ = 0.0f;

                // ---- layer-2 GEMM (f16 accum) + fused layer-3 MMA ----
#pragma unroll
                for (int ktp = 0; ktp < 4; ktp++) {
                    unsigned acc[2][2];   // [ntl][reg] packed half2
                    acc[0][0] = acc[0][1] = acc[1][0] = acc[1][1] = 0u;
#pragma unroll
                    for (int kt = 0; kt < 4; kt++) {
                        uint4 b = Bp[net][(ktp * 4 + kt) * 32 + lane];
                        mma16816_h(acc[0][0], acc[0][1],
                                   A[kt][0], A[kt][1], A[kt][2], A[kt][3],
                                   b.x, b.y);
                        mma16816_h(acc[1][0], acc[1][1],
                                   A[kt][0], A[kt][1], A[kt][2], A[kt][3],
                                   b.z, b.w);
                    }
                    // epilogue: h2 = silu(acc+b2) straight into layer-3 A-frag
                    __half2 bb0 = hb2[net][2 * ktp], bb1 = hb2[net][2 * ktp + 1];
                    __half2 a00 = *reinterpret_cast<__half2*>(&acc[0][0]);
                    __half2 a01 = *reinterpret_cast<__half2*>(&acc[0][1]);
                    __half2 a10 = *reinterpret_cast<__half2*>(&acc[1][0]);
                    __half2 a11 = *reinterpret_cast<__half2*>(&acc[1][1]);
                    unsigned e0 = silu2h(__hfma2(a00, h05, bb0));  // row g,   k lo
                    unsigned e1 = silu2h(__hfma2(a01, h05, bb0));  // row g+8, k lo
                    unsigned e2 = silu2h(__hfma2(a10, h05, bb1));  // row g,   k hi
                    unsigned e3 = silu2h(__hfma2(a11, h05, bb1));  // row g+8, k hi
                    if (ktp & 1)
                        mma16816_f(db0, db1_, db2_, db3_,
                                   e0, e1, e2, e3, bw3[net][ktp][0], bw3[net][ktp][1]);
                    else
                        mma16816_f(da0, da1, da2, da3,
                                   e0, e1, e2, e3, bw3[net][ktp][0], bw3[net][ktp][1]);
                }

                float d0 = da0 + db0;
                float d2 = da2 + db2_;
                // result col0: row g on (tg==0).d0, row g+8 on (tg==0).d2
                float v0 = __shfl_sync(0xffffffffu, d0, src);
                float v2 = __shfl_sync(0xffffffffu, d2, src);
                fg[net] = (lane & 8) ? v2 : v0;
            }

            // state update (dt = 1, sqrt_dt = 1)
            float graw = fg[1];
            float gval = fmaxf(graw, 0.0f)
                       + __logf(1.0f + __expf(-fabsf(graw))) + 1e-6f;
            z = z + kappa * (mu - z) + fg[0] + gval * xik;

            // loss: sigmoid(z) = 0.5 + 0.5*tanh(z/2)  (single MUFU, no divide)
            float th;
            asm("tanh.approx.f32 %0, %1;\n" : "=f"(th) : "f"(0.5f * z));
            float dy = yt - 0.5f * th;
            ssum = fmaf(dy, dy, ssum);
        }
    }

    // lanes 16-31 are mirrors: drop their duplicate sums
    if (lane >= 16) ssum = 0.0f;

    // deterministic reduction: warp -> CTA -> g_part
#pragma unroll
    for (int o = 16; o; o >>= 1) ssum += __shfl_xor_sync(0xffffffffu, ssum, o);
    if (lane == 0) red[warp] = ssum;
    __syncthreads();
    if (warp == 0) {
        float s = (lane < NWARPS) ? red[lane] : 0.0f;
#pragma unroll
        for (int o = 8; o; o >>= 1) s += __shfl_xor_sync(0xffffffffu, s, o);
        if (lane == 0) g_part[blockIdx.x] = s;
    }
}

// ---------------------------------------------------------------------------
// Finalize: reduce 148 partials, apply 0.5/sigma^2 and log-sigma terms
// ---------------------------------------------------------------------------
__global__ void fin_kernel(const float* __restrict__ lsop, float* __restrict__ out)
{
    int lane = threadIdx.x;                // 32 threads
    float s = 0.0f;
    for (int i = lane; i < NCTA; i += 32) s += g_part[i];
#pragma unroll
    for (int o = 16; o; o >>= 1) s += __shfl_xor_sync(0xffffffffu, s, o);
    if (lane == 0) {
        float lso = *lsop;
        float sig = expf(lso) + 1e-8f;
        out[0] = 0.5f * s / ((float)T_STEPS * (float)NMC) / (sig * sig) + lso;
    }
}

// ---------------------------------------------------------------------------
extern "C" void kernel_launch(void* const* d_in, const int* in_sizes, int n_in,
                              void* d_out, int out_size)
{
    const float* X_seq = (const float*)d_in[0];
    const float* y_seq = (const float*)d_in[1];
    const float* kappa = (const float*)d_in[2];
    const float* a     = (const float*)d_in[3];
    const float* b0    = (const float*)d_in[4];
    const float* b1    = (const float*)d_in[5];
    const float* b2    = (const float*)d_in[6];
    const float* S     = (const float*)d_in[7];
    const float* lso   = (const float*)d_in[8];
    const float* dW1   = (const float*)d_in[9];
    const float* db1   = (const float*)d_in[10];
    const float* dW2   = (const float*)d_in[11];
    const float* db2   = (const float*)d_in[12];
    const float* dW3   = (const float*)d_in[13];
    const float* db3   = (const float*)d_in[14];
    const float* gW1   = (const float*)d_in[15];
    const float* gb1   = (const float*)d_in[16];
    const float* gW2   = (const float*)d_in[17];
    const float* gb2   = (const float*)d_in[18];
    const float* gW3   = (const float*)d_in[19];
    const float* gb3   = (const float*)d_in[20];
    const float* xi    = (const float*)d_in[21];
    const int*   i0    = (const int*)d_in[22];

    prep_kernel<<<T_STEPS, 128>>>(X_seq, a, b0, b1, b2, S, dW1, db1, gW1, gb1, i0);
    main_kernel<<<NCTA, TPB>>>(y_seq, kappa, dW2, db2, dW3, db3,
                               gW2, gb2, gW3, gb3, xi, i0);
    fin_kernel<<<1, 32>>>(lso, (float*)d_out);
}